// round 1
// baseline (speedup 1.0000x reference)
#include <cuda_runtime.h>

#define D 1024
#define NB 8
#define NT 64
#define NS 32
#define NE 16
#define NV 50257

// Scratch (device globals — no allocation allowed)
__device__ float g_q[NB * NT * D];
__device__ float g_k[NB * NS * D];
__device__ float g_attn[NB * NT * NS];
__device__ float g_sal[NB * NS * NE];

__device__ __forceinline__ float warp_sum(float v) {
#pragma unroll
    for (int o = 16; o > 0; o >>= 1) v += __shfl_down_sync(0xffffffffu, v, o);
    return v;
}

// ---------------------------------------------------------------------------
// Fused q/k projection GEMM: C[M,1024] = A[M,1024] @ W[1024,1024] + bias
// blockIdx.z==0: q = x@Wq+bq (M=512); z==1: k = mem@Wk+bk (M=256)
// 64x64 tile, BK=16, 256 threads, 4x4 register micro-tile.
// ---------------------------------------------------------------------------
#define BM 64
#define BN 64
#define BK 16

__global__ __launch_bounds__(256) void qk_gemm(
    const float* __restrict__ x, const float* __restrict__ Wq, const float* __restrict__ bq,
    const float* __restrict__ mem, const float* __restrict__ Wk, const float* __restrict__ bk)
{
    const float* A; const float* W; const float* bias; float* C; int M;
    if (blockIdx.z == 0) { A = x;   W = Wq; bias = bq; C = g_q; M = NB * NT; }
    else                 { A = mem; W = Wk; bias = bk; C = g_k; M = NB * NS; }

    int row0 = blockIdx.y * BM;
    if (row0 >= M) return;
    int col0 = blockIdx.x * BN;

    __shared__ float As[BK][BM + 1];   // +1 pad: conflict-free transposed stores
    __shared__ float Bs[BK][BN];

    int tid = threadIdx.x;
    int tr = tid >> 4;           // 0..15
    int tc = tid & 15;           // 0..15
    int la_r = tid >> 2;         // 0..63  (A tile row)
    int la_c = (tid & 3) << 2;   // 0,4,8,12 (A tile col, float4)
    int lb_r = tid >> 4;         // 0..15  (B tile row)
    int lb_c = (tid & 15) << 2;  // 0..60  (B tile col, float4)

    float acc[4][4];
#pragma unroll
    for (int i = 0; i < 4; i++)
#pragma unroll
        for (int j = 0; j < 4; j++) acc[i][j] = 0.f;

    for (int k0 = 0; k0 < D; k0 += BK) {
        float4 a4 = *(const float4*)(A + (size_t)(row0 + la_r) * D + k0 + la_c);
        As[la_c + 0][la_r] = a4.x;
        As[la_c + 1][la_r] = a4.y;
        As[la_c + 2][la_r] = a4.z;
        As[la_c + 3][la_r] = a4.w;
        *(float4*)&Bs[lb_r][lb_c] =
            *(const float4*)(W + (size_t)(k0 + lb_r) * D + col0 + lb_c);
        __syncthreads();

#pragma unroll
        for (int kk = 0; kk < BK; kk++) {
            float a0 = As[kk][tr * 4 + 0];
            float a1 = As[kk][tr * 4 + 1];
            float a2 = As[kk][tr * 4 + 2];
            float a3 = As[kk][tr * 4 + 3];
            float4 b4 = *(float4*)&Bs[kk][tc * 4];
            acc[0][0] += a0 * b4.x; acc[0][1] += a0 * b4.y; acc[0][2] += a0 * b4.z; acc[0][3] += a0 * b4.w;
            acc[1][0] += a1 * b4.x; acc[1][1] += a1 * b4.y; acc[1][2] += a1 * b4.z; acc[1][3] += a1 * b4.w;
            acc[2][0] += a2 * b4.x; acc[2][1] += a2 * b4.y; acc[2][2] += a2 * b4.z; acc[2][3] += a2 * b4.w;
            acc[3][0] += a3 * b4.x; acc[3][1] += a3 * b4.y; acc[3][2] += a3 * b4.z; acc[3][3] += a3 * b4.w;
        }
        __syncthreads();
    }

    float4 bv = *(const float4*)(bias + col0 + tc * 4);
#pragma unroll
    for (int i = 0; i < 4; i++) {
        float* crow = C + (size_t)(row0 + tr * 4 + i) * D + col0 + tc * 4;
        crow[0] = acc[i][0] + bv.x;
        crow[1] = acc[i][1] + bv.y;
        crow[2] = acc[i][2] + bv.z;
        crow[3] = acc[i][3] + bv.w;
    }
}

// ---------------------------------------------------------------------------
// Per (b,t): scores -> softmax -> attn (saved), context, p_gen.
// 512 blocks, 256 threads.
// ---------------------------------------------------------------------------
__global__ __launch_bounds__(256) void attn_kernel(
    const float* __restrict__ x, const float* __restrict__ mem,
    const float* __restrict__ Wp, const float* __restrict__ bpv,
    float* __restrict__ out)  // p_gen at out[0..511]
{
    int bt = blockIdx.x;      // b*64 + t
    int b = bt >> 6;
    int tid = threadIdx.x;
    int lane = tid & 31, w = tid >> 5;

    __shared__ float qs[D];
    __shared__ float sc[NS];
    __shared__ float red[8];

    const float* qrow = g_q + (size_t)bt * D;
    for (int i = tid; i < D; i += 256) qs[i] = qrow[i];
    __syncthreads();

    // scores[s] = q . k_s / sqrt(D);  8 warps x 4 s each
#pragma unroll
    for (int j = 0; j < 4; j++) {
        int s = w * 4 + j;
        const float* krow = g_k + (size_t)(b * NS + s) * D;
        float p = 0.f;
        for (int d = lane; d < D; d += 32) p += qs[d] * krow[d];
        p = warp_sum(p);
        if (lane == 0) sc[s] = p * 0.03125f;  // 1/sqrt(1024)
    }
    __syncthreads();

    if (tid < 32) {
        float v = sc[tid];
        float m = v;
#pragma unroll
        for (int o = 16; o > 0; o >>= 1) m = fmaxf(m, __shfl_xor_sync(0xffffffffu, m, o));
        float e = expf(v - m);
        float sum = e;
#pragma unroll
        for (int o = 16; o > 0; o >>= 1) sum += __shfl_xor_sync(0xffffffffu, sum, o);
        float a = e / sum;
        sc[tid] = a;
        g_attn[(size_t)bt * NS + tid] = a;
    }
    __syncthreads();

    // context (fused into p_gen dot, never materialized)
    const float* xrow = x + (size_t)bt * D;
    const float* mb = mem + (size_t)b * NS * D;
    float acc = 0.f;
    for (int d = tid; d < D; d += 256) {
        float c = 0.f;
#pragma unroll 8
        for (int s = 0; s < NS; s++) c += sc[s] * mb[s * D + d];
        acc += xrow[d] * Wp[d] + c * Wp[D + d];
    }
    acc = warp_sum(acc);
    if (lane == 0) red[w] = acc;
    __syncthreads();
    if (tid == 0) {
        float v = 0.f;
#pragma unroll
        for (int i = 0; i < 8; i++) v += red[i];
        v += bpv[0];
        float z = (v - 0.5f) * 10.f;
        out[bt] = 1.f / (1.f + expf(-z));
    }
}

// ---------------------------------------------------------------------------
// Per (b,s): salience = softmax_E(dec_last . emb[ids]); zero all but the
// LAST occurrence of duplicated ids (scatter .set last-wins semantics).
// 256 blocks, 128 threads.
// ---------------------------------------------------------------------------
__global__ __launch_bounds__(128) void sal_kernel(
    const float* __restrict__ x, const float* __restrict__ emb, const int* __restrict__ ids)
{
    int bs = blockIdx.x;      // b*32 + s
    int b = bs >> 5;
    int tid = threadIdx.x, lane = tid & 31, w = tid >> 5;

    __shared__ float dl[D];
    __shared__ float sc[NE];
    __shared__ int id_s[NE];

    const float* xl = x + (size_t)(b * NT + NT - 1) * D;  // dec_last
    for (int i = tid; i < D; i += 128) dl[i] = xl[i];
    if (tid < NE) id_s[tid] = ids[(size_t)bs * NE + tid];
    __syncthreads();

#pragma unroll
    for (int j = 0; j < 4; j++) {
        int e = w * 4 + j;
        const float* er = emb + (size_t)id_s[e] * D;
        float p = 0.f;
        for (int d = lane; d < D; d += 32) p += dl[d] * er[d];
        p = warp_sum(p);
        if (lane == 0) sc[e] = p;
    }
    __syncthreads();

    if (tid == 0) {
        float m = sc[0];
        for (int e = 1; e < NE; e++) m = fmaxf(m, sc[e]);
        float a[NE];
        float sum = 0.f;
        for (int e = 0; e < NE; e++) { a[e] = expf(sc[e] - m); sum += a[e]; }
        float inv = 1.f / sum;
        for (int e = 0; e < NE; e++) {
            float val = a[e] * inv;
            for (int e2 = e + 1; e2 < NE; e2++)
                if (id_s[e2] == id_s[e]) { val = 0.f; break; }
            g_sal[(size_t)bs * NE + e] = val;
        }
    }
}

// ---------------------------------------------------------------------------
// Scatter: out[b,t, ids[b,s,e]] += attn[b,t,s] * sal[b,s,e]
// 256 blocks (b,s), 1024 threads (t,e).
// ---------------------------------------------------------------------------
__global__ __launch_bounds__(1024) void scatter_kernel(
    const int* __restrict__ ids, float* __restrict__ out)
{
    int bs = blockIdx.x;
    int b = bs >> 5, s = bs & 31;
    int tid = threadIdx.x;
    int t = tid >> 4, e = tid & 15;

    __shared__ float ws[NE];
    __shared__ int vs[NE];
    __shared__ float at[NT];

    if (tid < NE) {
        ws[tid] = g_sal[(size_t)bs * NE + tid];
        vs[tid] = ids[(size_t)bs * NE + tid];
    }
    if (tid < NT) at[tid] = g_attn[(size_t)(b * NT + tid) * NS + s];
    __syncthreads();

    float wgt = ws[e];
    if (wgt != 0.f) {
        float* dst = out + 512 + (size_t)(b * NT + t) * NV + vs[e];
        atomicAdd(dst, at[t] * wgt);
    }
}

// ---------------------------------------------------------------------------
extern "C" void kernel_launch(void* const* d_in, const int* in_sizes, int n_in,
                              void* d_out, int out_size)
{
    const float* x   = (const float*)d_in[0];   // decoder_states (8,64,1024)
    const float* mem = (const float*)d_in[1];   // scene_memory  (8,32,1024)
    const float* emb = (const float*)d_in[2];   // embedding_weight (V,1024)
    const int*   ids = (const int*)d_in[3];     // ent_ids (8,32,16)
    const float* Wq  = (const float*)d_in[4];
    const float* bq  = (const float*)d_in[5];
    const float* Wk  = (const float*)d_in[6];
    const float* bk  = (const float*)d_in[7];
    const float* Wp  = (const float*)d_in[8];   // (2048,1)
    const float* bp  = (const float*)d_in[9];   // (1,)
    float* out = (float*)d_out;

    // zero the whole output (p_gen region rewritten by attn_kernel)
    cudaMemsetAsync(d_out, 0, (size_t)out_size * sizeof(float));

    dim3 gg(D / BN, (NB * NT) / BM, 2);
    qk_gemm<<<gg, 256>>>(x, Wq, bq, mem, Wk, bk);
    attn_kernel<<<NB * NT, 256>>>(x, mem, Wp, bp, out);
    sal_kernel<<<NB * NS, 128>>>(x, emb, ids);
    scatter_kernel<<<NB * NS, 1024>>>(ids, out);
}

// round 3
// speedup vs baseline: 1.3739x; 1.3739x over previous
#include <cuda_runtime.h>
#include <cuda_bf16.h>
#include <cstdint>

#define D 1024
#define NB 8
#define NT 64
#define NS 32
#define NE 16
#define NV 50257
#define M_TOT 768          // 512 q rows + 256 k rows

// tcgen05 only exists in the arch-SPECIFIC (sm_103a) device pass.
#if defined(__CUDA_ARCH_FEAT_SM103_ALL) || \
    (defined(__CUDA_ARCH_SPECIFIC__) && (__CUDA_ARCH_SPECIFIC__ == 1030))
#define HAS_TCGEN05 1
#else
#define HAS_TCGEN05 0
#endif

// ---------------- scratch (device globals; no allocation allowed) ----------
__device__ __nv_bfloat16 g_ahi[M_TOT * D];
__device__ __nv_bfloat16 g_alo[M_TOT * D];
__device__ __nv_bfloat16 g_whi[2 * D * D];   // transposed: [z][n][k]
__device__ __nv_bfloat16 g_wlo[2 * D * D];
__device__ float g_qk[M_TOT * D];            // rows 0-511: q, 512-767: k
__device__ float g_attn[NB * NT * NS];
__device__ float g_sal[NB * NS * NE];

// ---------------- PTX helpers ---------------------------------------------
__device__ __forceinline__ uint32_t smem_u32(const void* p) {
    uint32_t a;
    asm("{ .reg .u64 t; cvta.to.shared.u64 t, %1; cvt.u32.u64 %0, t; }"
        : "=r"(a) : "l"(p));
    return a;
}
__device__ __forceinline__ uint32_t elect1() {
    uint32_t p;
    asm volatile("{\n\t.reg .pred p;\n\telect.sync _|p, 0xFFFFFFFF;\n\t"
                 "selp.b32 %0, 1, 0, p;\n\t}" : "=r"(p));
    return p;
}
#define MBARRIER_INIT(a, c) \
    asm volatile("mbarrier.init.shared.b64 [%0], %1;" :: "r"(a), "r"(c) : "memory")
#define MBARRIER_INVAL(a) \
    asm volatile("mbarrier.inval.shared.b64 [%0];" :: "r"(a) : "memory")
#define MBARRIER_WAIT_PARITY(mb, ph) do {                                        \
    uint32_t _m = (mb), _p = (ph), _d;                                           \
    asm volatile("{\n\t.reg .pred p;\n\t"                                        \
        "mbarrier.try_wait.parity.acquire.cta.shared::cta.b64 p, [%1], %2;\n\t"  \
        "selp.b32 %0, 1, 0, p;\n\t}" : "=r"(_d) : "r"(_m), "r"(_p) : "memory");  \
    if (!_d) {                                                                   \
        asm volatile("{\n\t.reg .pred P1;\n\t"                                   \
          "WL_%=:\n\t"                                                           \
          "mbarrier.try_wait.parity.acquire.cta.shared::cta.b64 P1, [%0], %1, 0x989680;\n\t" \
          "@P1 bra.uni WD_%=;\n\t"                                               \
          "bra.uni WL_%=;\n\t"                                                   \
          "WD_%=:\n\t}" :: "r"(_m), "r"(_p) : "memory");                         \
    }                                                                            \
} while (0)

#if HAS_TCGEN05
#define TCGEN05_ALLOC(sa, n) \
    asm volatile("tcgen05.alloc.cta_group::1.sync.aligned.shared::cta.b32 [%0], %1;" \
                 :: "r"((uint32_t)(sa)), "r"((uint32_t)(n)) : "memory")
#define TCGEN05_DEALLOC(t, n) \
    asm volatile("tcgen05.dealloc.cta_group::1.sync.aligned.b32 %0, %1;" :: "r"(t), "r"(n))
#define TCGEN05_RELINQ() \
    asm volatile("tcgen05.relinquish_alloc_permit.cta_group::1.sync.aligned;")
#define TCGEN05_COMMIT(mb) \
    asm volatile("tcgen05.commit.cta_group::1.mbarrier::arrive::one.shared::cluster.b64 [%0];" \
                 :: "r"((uint32_t)(mb)) : "memory")
#define TCGEN05_FENCE_AFTER() \
    asm volatile("tcgen05.fence::after_thread_sync;" ::: "memory")
#define TCGEN05_FENCE_BEFORE() \
    asm volatile("tcgen05.fence::before_thread_sync;" ::: "memory")
#define TCGEN05_WAIT_LD() asm volatile("tcgen05.wait::ld.sync.aligned;" ::: "memory")
#define FENCE_PROXY_ASYNC() \
    asm volatile("fence.proxy.async.shared::cta;" ::: "memory")
#define TCGEN05_LD_32X32B_X32(r, ta) \
    asm volatile( \
        "tcgen05.ld.sync.aligned.32x32b.x32.b32 " \
        "{%0, %1, %2, %3, %4, %5, %6, %7, " \
        " %8, %9, %10, %11, %12, %13, %14, %15, " \
        " %16, %17, %18, %19, %20, %21, %22, %23, " \
        " %24, %25, %26, %27, %28, %29, %30, %31}, [%32];" \
        : "=r"((r)[0]),  "=r"((r)[1]),  "=r"((r)[2]),  "=r"((r)[3]), \
          "=r"((r)[4]),  "=r"((r)[5]),  "=r"((r)[6]),  "=r"((r)[7]), \
          "=r"((r)[8]),  "=r"((r)[9]),  "=r"((r)[10]), "=r"((r)[11]), \
          "=r"((r)[12]), "=r"((r)[13]), "=r"((r)[14]), "=r"((r)[15]), \
          "=r"((r)[16]), "=r"((r)[17]), "=r"((r)[18]), "=r"((r)[19]), \
          "=r"((r)[20]), "=r"((r)[21]), "=r"((r)[22]), "=r"((r)[23]), \
          "=r"((r)[24]), "=r"((r)[25]), "=r"((r)[26]), "=r"((r)[27]), \
          "=r"((r)[28]), "=r"((r)[29]), "=r"((r)[30]), "=r"((r)[31]) \
        : "r"(ta))

__device__ __forceinline__ void mma_f16_ss(uint32_t d, uint64_t a, uint64_t b,
                                           uint32_t idesc, uint32_t en) {
    asm volatile("{\n\t.reg .pred p;\n\tsetp.ne.u32 p, %5, 0;\n\t"
        "tcgen05.mma.cta_group::1.kind::f16 [%0], %1, %2, %3, {%4,%4,%4,%4}, p;\n\t}"
        :: "r"(d), "l"(a), "l"(b), "r"(idesc), "r"(0u), "r"(en) : "memory");
}
#endif  // HAS_TCGEN05

#define SWZ(b) ((b) ^ (((b) >> 3) & 0x70))
static constexpr uint64_t DESC_BASE_SW128 =
    (uint64_t(2) << 61) | (uint64_t(1) << 46) | (uint64_t(64) << 32) | (uint64_t(1) << 16);
#define MAKE_DESC(a) (DESC_BASE_SW128 | ((uint64_t)((a) >> 4) & 0x3FFF))

// idesc: kind::f16, dtype=F32(1<<4), atype=BF16(1<<7), btype=BF16(1<<10),
// N=128 -> (128/8)<<17, M=128 -> (128/16)<<24  => 0x8200490
static constexpr uint32_t GEMM_IDESC =
    (1u << 4) | (1u << 7) | (1u << 10) | ((128u / 8u) << 17) | ((128u / 16u) << 24);

__device__ __forceinline__ float warp_sum(float v) {
#pragma unroll
    for (int o = 16; o > 0; o >>= 1) v += __shfl_down_sync(0xffffffffu, v, o);
    return v;
}

// ---------------------------------------------------------------------------
// fp32 -> bf16 hi/lo split of [x ; mem] into g_ahi/g_alo (768 x 1024)
// ---------------------------------------------------------------------------
__global__ __launch_bounds__(256) void cvt_inputs(
    const float* __restrict__ x, const float* __restrict__ mem)
{
    int i = blockIdx.x * 256 + threadIdx.x;        // float4 index, 196608 total
    const float4* src = (i < 131072) ? ((const float4*)x + i)
                                     : ((const float4*)mem + (i - 131072));
    float4 v = *src;
    int base = i * 4;
    float f[4] = {v.x, v.y, v.z, v.w};
#pragma unroll
    for (int j = 0; j < 4; j++) {
        __nv_bfloat16 h = __float2bfloat16(f[j]);
        g_ahi[base + j] = h;
        g_alo[base + j] = __float2bfloat16(f[j] - __bfloat162float(h));
    }
}

// ---------------------------------------------------------------------------
// Transpose + split W: g_whi/g_wlo[z][n][k] = split(W_z[k][n])
// ---------------------------------------------------------------------------
__global__ __launch_bounds__(256) void cvt_w(
    const float* __restrict__ Wq, const float* __restrict__ Wk)
{
    __shared__ float t[32][33];
    const float* W = blockIdx.z ? Wk : Wq;
    size_t zoff = (size_t)blockIdx.z * D * D;
    int n0 = blockIdx.x * 32, k0 = blockIdx.y * 32;
    int tx = threadIdx.x, ty = threadIdx.y;
#pragma unroll
    for (int j = 0; j < 4; j++)
        t[ty + j * 8][tx] = W[(size_t)(k0 + ty + j * 8) * D + n0 + tx];
    __syncthreads();
#pragma unroll
    for (int j = 0; j < 4; j++) {
        float v = t[tx][ty + j * 8];                 // = W[k0+tx][n0+ty+j*8]
        size_t o = zoff + (size_t)(n0 + ty + j * 8) * D + k0 + tx;
        __nv_bfloat16 h = __float2bfloat16(v);
        g_whi[o] = h;
        g_wlo[o] = __float2bfloat16(v - __bfloat162float(h));
    }
}

// ---------------------------------------------------------------------------
// GEMM: g_qk[m][n] = sum_k A[m][k] * W_z[k][n] + bias.  grid (8,6), 256 thr.
// sm_103a pass: tcgen05 bf16x3 (hi*hi + hi*lo + lo*hi), fp32 TMEM accum.
// compute_103 pass: SIMT fp32 128x128 tile fallback (reads fp32 inputs).
// ---------------------------------------------------------------------------
#define SM_MBAR  0
#define SM_TPTR  16
#define SM_AHI   1024
#define SM_ALO   (SM_AHI + 16384)
#define SM_BHI   (SM_ALO + 16384)
#define SM_BLO   (SM_BHI + 16384)
#define SM_TOTAL (SM_BLO + 16384)

#if HAS_TCGEN05
__device__ __forceinline__ void load_tile(char* smem, int off,
                                          const __nv_bfloat16* __restrict__ src)
{
    int tid = threadIdx.x;
#pragma unroll
    for (int i = 0; i < 4; i++) {
        int idx = tid + i * 256;                    // 0..1023
        int row = idx >> 3, c8 = idx & 7;
        uint32_t b = row * 128 + c8 * 16;
        *(float4*)(smem + off + SWZ(b)) =
            *(const float4*)(src + (size_t)row * D + c8 * 8);
    }
}
#endif

__global__ __launch_bounds__(256, 1) void mma_gemm(
    const float* __restrict__ x, const float* __restrict__ mem,
    const float* __restrict__ Wq, const float* __restrict__ Wk,
    const float* __restrict__ bq, const float* __restrict__ bk)
{
    extern __shared__ char smem[];
    int tid = threadIdx.x;
    int tn = blockIdx.x, tm = blockIdx.y;
    int m0 = tm * 128, n0 = tn * 128;

#if HAS_TCGEN05
    (void)x; (void)mem; (void)Wq; (void)Wk;
    uint32_t sb = smem_u32(smem);
    int wid = tid >> 5, lane = tid & 31;
    int z = (tm >= 4);       // tiles 0-3: q rows (Wq), 4-5: k rows (Wk)

    const __nv_bfloat16* ahi = g_ahi + (size_t)m0 * D;
    const __nv_bfloat16* alo = g_alo + (size_t)m0 * D;
    const __nv_bfloat16* bhi = g_whi + (size_t)z * D * D + (size_t)n0 * D;
    const __nv_bfloat16* blo = g_wlo + (size_t)z * D * D + (size_t)n0 * D;

    if (wid == 0) TCGEN05_ALLOC(sb + SM_TPTR, 128);
    if (tid == 0) MBARRIER_INIT(sb + SM_MBAR, 1);
    __syncthreads();
    uint32_t tmem;
    asm volatile("ld.shared.b32 %0, [%1];" : "=r"(tmem) : "r"(sb + SM_TPTR));

    for (int c = 0; c < 16; c++) {
        if (c) MBARRIER_WAIT_PARITY(sb + SM_MBAR, (c - 1) & 1);
        load_tile(smem, SM_AHI, ahi + c * 64);
        load_tile(smem, SM_ALO, alo + c * 64);
        load_tile(smem, SM_BHI, bhi + c * 64);
        load_tile(smem, SM_BLO, blo + c * 64);
        __syncthreads();
        if (wid == 0 && elect1()) {
            FENCE_PROXY_ASYNC();
            uint64_t dah = MAKE_DESC(sb + SM_AHI);
            uint64_t dal = MAKE_DESC(sb + SM_ALO);
            uint64_t dbh = MAKE_DESC(sb + SM_BHI);
            uint64_t dbl = MAKE_DESC(sb + SM_BLO);
#pragma unroll
            for (int s = 0; s < 4; s++) {
                uint64_t o = s * 2;                 // K=16 step = 32B = 2 units
                mma_f16_ss(tmem, dah + o, dbh + o, GEMM_IDESC, !(c == 0 && s == 0));
                mma_f16_ss(tmem, dah + o, dbl + o, GEMM_IDESC, 1u);
                mma_f16_ss(tmem, dal + o, dbh + o, GEMM_IDESC, 1u);
            }
            TCGEN05_COMMIT(sb + SM_MBAR);
        }
    }
    MBARRIER_WAIT_PARITY(sb + SM_MBAR, 1);          // chunk 15 -> parity 1
    TCGEN05_FENCE_AFTER();

    if (wid < 4) {
        uint32_t dr[128];
#pragma unroll
        for (int b = 0; b < 128; b += 32) TCGEN05_LD_32X32B_X32(dr + b, tmem + b);
        TCGEN05_WAIT_LD();
        TCGEN05_FENCE_BEFORE();
        int m = m0 + wid * 32 + lane;
        const float* bias = (m < 512) ? bq : bk;
        float* crow = g_qk + (size_t)m * D + n0;
#pragma unroll 8
        for (int cc = 0; cc < 128; cc++)
            crow[cc] = __uint_as_float(dr[cc]) + __ldg(&bias[n0 + cc]);
    }
    __syncthreads();
    if (tid == 0) MBARRIER_INVAL(sb + SM_MBAR);
    __syncthreads();
    if (wid == 0) {
        TCGEN05_RELINQ();
        TCGEN05_DEALLOC(tmem, 128);
    }
#else
    // ---------------- SIMT fp32 fallback: 128x128 tile, BK=16, 8x8 micro ---
    float* As = (float*)smem;                    // [16][132] transposed A
    float* Bs = (float*)(smem + 16 * 132 * 4);   // [16][128]
    const float* Asrc = (m0 < 512) ? (x + (size_t)m0 * D)
                                   : (mem + (size_t)(m0 - 512) * D);
    const float* W = (m0 < 512) ? Wq : Wk;
    const float* bias = (m0 < 512) ? bq : bk;
    int tr = tid >> 4, tc = tid & 15;

    float acc[8][8];
#pragma unroll
    for (int i = 0; i < 8; i++)
#pragma unroll
        for (int j = 0; j < 8; j++) acc[i][j] = 0.f;

    for (int k0 = 0; k0 < D; k0 += 16) {
#pragma unroll
        for (int i = 0; i < 2; i++) {
            int f4 = tid * 2 + i;                // 0..511
            int row = f4 >> 2;                   // 0..127
            int c4 = (f4 & 3) * 4;               // 0,4,8,12
            float4 v = *(const float4*)(Asrc + (size_t)row * D + k0 + c4);
            As[(c4 + 0) * 132 + row] = v.x;
            As[(c4 + 1) * 132 + row] = v.y;
            As[(c4 + 2) * 132 + row] = v.z;
            As[(c4 + 3) * 132 + row] = v.w;
        }
#pragma unroll
        for (int i = 0; i < 2; i++) {
            int f4 = tid * 2 + i;
            int row = f4 >> 5;                   // 0..15
            int cc = (f4 & 31) * 4;
            *(float4*)(Bs + row * 128 + cc) =
                *(const float4*)(W + (size_t)(k0 + row) * D + n0 + cc);
        }
        __syncthreads();
#pragma unroll
        for (int kk = 0; kk < 16; kk++) {
            float a[8], bb[8];
#pragma unroll
            for (int i = 0; i < 8; i++) a[i] = As[kk * 132 + tr * 8 + i];
#pragma unroll
            for (int j = 0; j < 8; j++) bb[j] = Bs[kk * 128 + tc * 8 + j];
#pragma unroll
            for (int i = 0; i < 8; i++)
#pragma unroll
                for (int j = 0; j < 8; j++) acc[i][j] += a[i] * bb[j];
        }
        __syncthreads();
    }
#pragma unroll
    for (int i = 0; i < 8; i++) {
        int m = m0 + tr * 8 + i;
        float* crow = g_qk + (size_t)m * D + n0 + tc * 8;
#pragma unroll
        for (int j = 0; j < 8; j++) crow[j] = acc[i][j] + bias[n0 + tc * 8 + j];
    }
#endif
}

// ---------------------------------------------------------------------------
// Per (b,t): scores -> softmax -> attn (saved), context, p_gen.
// ---------------------------------------------------------------------------
__global__ __launch_bounds__(256) void attn_kernel(
    const float* __restrict__ x, const float* __restrict__ mem,
    const float* __restrict__ Wp, const float* __restrict__ bpv,
    float* __restrict__ out)
{
    int bt = blockIdx.x;
    int b = bt >> 6;
    int tid = threadIdx.x;
    int lane = tid & 31, w = tid >> 5;

    __shared__ float qs[D];
    __shared__ float sc[NS];
    __shared__ float red[8];

    const float* qrow = g_qk + (size_t)bt * D;
    for (int i = tid; i < D; i += 256) qs[i] = qrow[i];
    __syncthreads();

#pragma unroll
    for (int j = 0; j < 4; j++) {
        int s = w * 4 + j;
        const float* krow = g_qk + (size_t)(512 + b * NS + s) * D;
        float p = 0.f;
        for (int d = lane; d < D; d += 32) p += qs[d] * krow[d];
        p = warp_sum(p);
        if (lane == 0) sc[s] = p * 0.03125f;
    }
    __syncthreads();

    if (tid < 32) {
        float v = sc[tid];
        float m = v;
#pragma unroll
        for (int o = 16; o > 0; o >>= 1) m = fmaxf(m, __shfl_xor_sync(0xffffffffu, m, o));
        float e = expf(v - m);
        float sum = e;
#pragma unroll
        for (int o = 16; o > 0; o >>= 1) sum += __shfl_xor_sync(0xffffffffu, sum, o);
        float a = e / sum;
        sc[tid] = a;
        g_attn[(size_t)bt * NS + tid] = a;
    }
    __syncthreads();

    const float* xrow = x + (size_t)bt * D;
    const float* mb = mem + (size_t)b * NS * D;
    float acc = 0.f;
    for (int d = tid; d < D; d += 256) {
        float c = 0.f;
#pragma unroll 8
        for (int s = 0; s < NS; s++) c += sc[s] * mb[s * D + d];
        acc += xrow[d] * Wp[d] + c * Wp[D + d];
    }
    acc = warp_sum(acc);
    if (lane == 0) red[w] = acc;
    __syncthreads();
    if (tid == 0) {
        float v = 0.f;
#pragma unroll
        for (int i = 0; i < 8; i++) v += red[i];
        v += bpv[0];
        float zz = (v - 0.5f) * 10.f;
        out[bt] = 1.f / (1.f + expf(-zz));
    }
}

// ---------------------------------------------------------------------------
// Per (b,s): salience softmax; last-wins dedup of duplicate ids.
// ---------------------------------------------------------------------------
__global__ __launch_bounds__(128) void sal_kernel(
    const float* __restrict__ x, const float* __restrict__ emb, const int* __restrict__ ids)
{
    int bs = blockIdx.x;
    int b = bs >> 5;
    int tid = threadIdx.x, lane = tid & 31, w = tid >> 5;

    __shared__ float dl[D];
    __shared__ float sc[NE];
    __shared__ int id_s[NE];

    const float* xl = x + (size_t)(b * NT + NT - 1) * D;
    for (int i = tid; i < D; i += 128) dl[i] = xl[i];
    if (tid < NE) id_s[tid] = ids[(size_t)bs * NE + tid];
    __syncthreads();

#pragma unroll
    for (int j = 0; j < 4; j++) {
        int e = w * 4 + j;
        const float* er = emb + (size_t)id_s[e] * D;
        float p = 0.f;
        for (int d = lane; d < D; d += 32) p += dl[d] * er[d];
        p = warp_sum(p);
        if (lane == 0) sc[e] = p;
    }
    __syncthreads();

    if (tid == 0) {
        float m = sc[0];
        for (int e = 1; e < NE; e++) m = fmaxf(m, sc[e]);
        float a[NE];
        float sum = 0.f;
        for (int e = 0; e < NE; e++) { a[e] = expf(sc[e] - m); sum += a[e]; }
        float inv = 1.f / sum;
        for (int e = 0; e < NE; e++) {
            float val = a[e] * inv;
            for (int e2 = e + 1; e2 < NE; e2++)
                if (id_s[e2] == id_s[e]) { val = 0.f; break; }
            g_sal[(size_t)bs * NE + e] = val;
        }
    }
}

// ---------------------------------------------------------------------------
// Scatter: out[b,t, ids[b,s,e]] += attn[b,t,s] * sal[b,s,e]
// ---------------------------------------------------------------------------
__global__ __launch_bounds__(1024) void scatter_kernel(
    const int* __restrict__ ids, float* __restrict__ out)
{
    int bs = blockIdx.x;
    int b = bs >> 5, s = bs & 31;
    int tid = threadIdx.x;
    int t = tid >> 4, e = tid & 15;

    __shared__ float ws[NE];
    __shared__ int vs[NE];
    __shared__ float at[NT];

    if (tid < NE) {
        ws[tid] = g_sal[(size_t)bs * NE + tid];
        vs[tid] = ids[(size_t)bs * NE + tid];
    }
    if (tid < NT) at[tid] = g_attn[(size_t)(b * NT + tid) * NS + s];
    __syncthreads();

    float wgt = ws[e];
    if (wgt != 0.f) {
        float* dst = out + 512 + (size_t)(b * NT + t) * NV + vs[e];
        atomicAdd(dst, at[t] * wgt);
    }
}

// ---------------------------------------------------------------------------
extern "C" void kernel_launch(void* const* d_in, const int* in_sizes, int n_in,
                              void* d_out, int out_size)
{
    const float* x   = (const float*)d_in[0];
    const float* mem = (const float*)d_in[1];
    const float* emb = (const float*)d_in[2];
    const int*   ids = (const int*)d_in[3];
    const float* Wq  = (const float*)d_in[4];
    const float* bq  = (const float*)d_in[5];
    const float* Wk  = (const float*)d_in[6];
    const float* bk  = (const float*)d_in[7];
    const float* Wp  = (const float*)d_in[8];
    const float* bp  = (const float*)d_in[9];
    float* out = (float*)d_out;

    cudaFuncSetAttribute(mma_gemm, cudaFuncAttributeMaxDynamicSharedMemorySize, SM_TOTAL);

    cudaMemsetAsync(d_out, 0, (size_t)out_size * sizeof(float));

    cvt_inputs<<<768, 256>>>(x, mem);
    cvt_w<<<dim3(32, 32, 2), dim3(32, 8)>>>(Wq, Wk);
    mma_gemm<<<dim3(8, 6), 256, SM_TOTAL>>>(x, mem, Wq, Wk, bq, bk);
    attn_kernel<<<NB * NT, 256>>>(x, mem, Wp, bp, out);
    sal_kernel<<<NB * NS, 128>>>(x, emb, ids);
    scatter_kernel<<<NB * NS, 1024>>>(ids, out);
}